// round 12
// baseline (speedup 1.0000x reference)
#include <cuda_runtime.h>
#include <cuda_bf16.h>
#include <math.h>
#include <stdint.h>

#define BB 4
#define SS 2048
#define DD 512
#define HH 8
#define DKK 64
#define DFF 2048
#define MROWS (BB * SS)   // 8192

// ---------------- scratch (static device globals; no allocations) ----------
__device__ float g_ctx[MROWS * DD];
__device__ float g_attres[MROWS * DD];
__device__ float g_h[MROWS * DD];
__device__ float g_ff[MROWS * DFF];
// bf16 hi/lo weights
__device__ __nv_bfloat16 g_wqkvh[3 * DD * DD];
__device__ __nv_bfloat16 g_wqkvl[3 * DD * DD];
__device__ __nv_bfloat16 g_wph[DD * DD];
__device__ __nv_bfloat16 g_wpl[DD * DD];
__device__ __nv_bfloat16 g_w1h[DFF * DD];
__device__ __nv_bfloat16 g_w1l[DFF * DD];
__device__ __nv_bfloat16 g_w2h[DD * DFF];
__device__ __nv_bfloat16 g_w2l[DD * DFF];
// bf16 hi/lo activations (q,k,v stacked)
__device__ __nv_bfloat16 g_qkvh[3 * MROWS * DD];
__device__ __nv_bfloat16 g_qkvl[3 * MROWS * DD];

// ================= helpers =================================================
__device__ __forceinline__ uint32_t smem_u32(const void* p) {
    uint32_t a;
    asm("{ .reg .u64 t; cvta.to.shared.u64 t, %1; cvt.u32.u64 %0, t; }"
        : "=r"(a) : "l"(p));
    return a;
}
__device__ __forceinline__ void ldm_x4(uint32_t& r0, uint32_t& r1,
                                       uint32_t& r2, uint32_t& r3, uint32_t addr) {
    asm volatile("ldmatrix.sync.aligned.m8n8.x4.shared.b16 {%0,%1,%2,%3}, [%4];"
                 : "=r"(r0), "=r"(r1), "=r"(r2), "=r"(r3) : "r"(addr));
}
__device__ __forceinline__ void ldm_x4_t(uint32_t& r0, uint32_t& r1,
                                         uint32_t& r2, uint32_t& r3, uint32_t addr) {
    asm volatile("ldmatrix.sync.aligned.m8n8.x4.trans.shared.b16 {%0,%1,%2,%3}, [%4];"
                 : "=r"(r0), "=r"(r1), "=r"(r2), "=r"(r3) : "r"(addr));
}
__device__ __forceinline__ void mma_bf16(float* d, const uint32_t* a,
                                         const uint32_t* b) {
    asm volatile(
        "mma.sync.aligned.m16n8k16.row.col.f32.bf16.bf16.f32 "
        "{%0,%1,%2,%3}, {%4,%5,%6,%7}, {%8,%9}, {%0,%1,%2,%3};"
        : "+f"(d[0]), "+f"(d[1]), "+f"(d[2]), "+f"(d[3])
        : "r"(a[0]), "r"(a[1]), "r"(a[2]), "r"(a[3]), "r"(b[0]), "r"(b[1]));
}
__device__ __forceinline__ uint32_t pack_hi(float a, float b, float& la, float& lb) {
    __nv_bfloat162 h = __floats2bfloat162_rn(a, b);
    la = a - __bfloat162float(h.x);
    lb = b - __bfloat162float(h.y);
    union { __nv_bfloat162 v; uint32_t u; } cv; cv.v = h;
    return cv.u;
}
__device__ __forceinline__ uint32_t pack_bf(float a, float b) {
    __nv_bfloat162 h = __floats2bfloat162_rn(a, b);
    union { __nv_bfloat162 v; uint32_t u; } cv; cv.v = h;
    return cv.u;
}
// 128B-row swizzle (8 x 16B chunks)
__device__ __forceinline__ uint32_t offsw(uint32_t row, uint32_t chunk) {
    return row * 128u + ((chunk ^ (row & 7u)) << 4);
}
__device__ __forceinline__ void cpa16(uint32_t dst, const void* src) {
    asm volatile("cp.async.cg.shared.global [%0], [%1], 16;"
                 :: "r"(dst), "l"(src) : "memory");
}

// ---------------- weight prep: fp32 -> bf16 hi/lo --------------------------
__global__ __launch_bounds__(256) void prep_w(
    const float* __restrict__ s, __nv_bfloat16* __restrict__ hi,
    __nv_bfloat16* __restrict__ lo)
{
    const int i = blockIdx.x * 256 + threadIdx.x;    // float4 index
    const float4 f = *(const float4*)&s[(size_t)i * 4];
    float la, lb, lc, ld;
    uint32_t h0 = pack_hi(f.x, f.y, la, lb);
    uint32_t h1 = pack_hi(f.z, f.w, lc, ld);
    *(uint2*)&hi[(size_t)i * 4] = make_uint2(h0, h1);
    *(uint2*)&lo[(size_t)i * 4] = make_uint2(pack_bf(la, lb), pack_bf(lc, ld));
}

// ============ HMMA bf16x3 GEMM: C[m,n] = sum_k A[m,k]*W[n,k] ===============
// A fp32 (cvt in kernel); B pre-split bf16 hi/lo. 128x128 tile, BK=32, 8 warps.
// EPI: 1 +res, 2 +bias->GELU, 3 +bias+res, 4 write bf16 hi/lo (QKV, z-indexed)
template <int EPI>
__global__ __launch_bounds__(256, 2) void gemm_h2(
    const float* __restrict__ A,
    const __nv_bfloat16* __restrict__ Bh_, const __nv_bfloat16* __restrict__ Bl_,
    const float* __restrict__ bias, const float* __restrict__ res,
    float* __restrict__ C,
    __nv_bfloat16* __restrict__ Oh_, __nv_bfloat16* __restrict__ Ol_,
    int M, int N, int K)
{
    __shared__ __align__(16) uint8_t sm[32768];
    const uint32_t sb = smem_u32(sm);
    const uint32_t AH = 0, AL = 8192, BH = 16384, BL = 24576;

    const int tid = threadIdx.x;
    const int lane = tid & 31;
    const int warp = tid >> 5;
    const int wm = warp >> 2;
    const int wn = warp & 3;
    const int bm = blockIdx.y * 128;
    const int bn = blockIdx.x * 128;

    const __nv_bfloat16* Bh = Bh_;
    const __nv_bfloat16* Bl = Bl_;
    __nv_bfloat16* Oh = Oh_;
    __nv_bfloat16* Ol = Ol_;
    float scale = 1.f;
    if (EPI == 4) {
        const int z = blockIdx.z;
        Bh += (size_t)z * N * K; Bl += (size_t)z * N * K;
        Oh += (size_t)z * M * N; Ol += (size_t)z * M * N;
        if (z == 0) scale = 0.125f;
    }

    float acc[4][4][4];
#pragma unroll
    for (int i = 0; i < 4; i++)
#pragma unroll
        for (int j = 0; j < 4; j++)
#pragma unroll
            for (int e = 0; e < 4; e++) acc[i][j][e] = 0.f;

    const int arow = lane & 15;
    const int akc  = lane >> 4;
    const int brow = ((lane >> 4) << 3) + (lane & 7);
    const int bkc  = (lane >> 3) & 1;
    const uint32_t asw = (uint32_t)(arow & 3);
    const uint32_t bsw = (uint32_t)(brow & 3);

    const int nslab = K >> 5;

    // prologue: load slab 0 into regs
    float4 av[4];
    uint4 bhv[2], blv[2];
#pragma unroll
    for (int i = 0; i < 4; i++) {
        const int idx = tid + i * 256;
        const int r = idx >> 3, c4 = idx & 7;
        av[i] = *(const float4*)&A[(size_t)(bm + r) * K + c4 * 4];
    }
#pragma unroll
    for (int i = 0; i < 2; i++) {
        const int slot = tid + i * 256;
        const int r = slot >> 2, ch = slot & 3;
        bhv[i] = *(const uint4*)&Bh[(size_t)(bn + r) * K + ch * 8];
        blv[i] = *(const uint4*)&Bl[(size_t)(bn + r) * K + ch * 8];
    }

    for (int t = 0; t < nslab; t++) {
        __syncthreads();  // previous mma done reading smem

        // ---- store current slab to smem ----
#pragma unroll
        for (int i = 0; i < 4; i++) {
            const int idx = tid + i * 256;
            const int r = idx >> 3, c4 = idx & 7;
            const uint32_t chunk = (uint32_t)(c4 >> 1);
            const uint32_t off = (uint32_t)r * 64 +
                                 ((chunk ^ (uint32_t)(r & 3)) << 4) + (c4 & 1) * 8;
            float lx, ly, lz, lw;
            uint32_t h0 = pack_hi(av[i].x, av[i].y, lx, ly);
            uint32_t h1 = pack_hi(av[i].z, av[i].w, lz, lw);
            *(uint2*)(sm + AH + off) = make_uint2(h0, h1);
            *(uint2*)(sm + AL + off) = make_uint2(pack_bf(lx, ly), pack_bf(lz, lw));
        }
#pragma unroll
        for (int i = 0; i < 2; i++) {
            const int slot = tid + i * 256;
            const int r = slot >> 2, ch = slot & 3;
            const uint32_t off = (uint32_t)r * 64 +
                                 (((uint32_t)ch ^ (uint32_t)(r & 3)) << 4);
            *(uint4*)(sm + BH + off) = bhv[i];
            *(uint4*)(sm + BL + off) = blv[i];
        }
        __syncthreads();

        // ---- prefetch next slab into regs (overlaps with mma below) ----
        if (t + 1 < nslab) {
            const int k0 = (t + 1) << 5;
#pragma unroll
            for (int i = 0; i < 4; i++) {
                const int idx = tid + i * 256;
                const int r = idx >> 3, c4 = idx & 7;
                av[i] = *(const float4*)&A[(size_t)(bm + r) * K + k0 + c4 * 4];
            }
#pragma unroll
            for (int i = 0; i < 2; i++) {
                const int slot = tid + i * 256;
                const int r = slot >> 2, ch = slot & 3;
                bhv[i] = *(const uint4*)&Bh[(size_t)(bn + r) * K + k0 + ch * 8];
                blv[i] = *(const uint4*)&Bl[(size_t)(bn + r) * K + k0 + ch * 8];
            }
        }

        // ---- mma phase ----
#pragma unroll
        for (int ks = 0; ks < 2; ks++) {
            const uint32_t kca = (uint32_t)(ks * 2 + akc);
            const uint32_t kcb = (uint32_t)(ks * 2 + bkc);

            uint32_t bh[2][4], bl[2][4];
#pragma unroll
            for (int p = 0; p < 2; p++) {
                const uint32_t row = (uint32_t)(wn * 32 + p * 16 + brow);
                const uint32_t off = row * 64 + ((kcb ^ bsw) << 4);
                ldm_x4(bh[p][0], bh[p][1], bh[p][2], bh[p][3], sb + BH + off);
                ldm_x4(bl[p][0], bl[p][1], bl[p][2], bl[p][3], sb + BL + off);
            }
#pragma unroll
            for (int mf = 0; mf < 4; mf++) {
                const uint32_t row = (uint32_t)(wm * 64 + mf * 16 + arow);
                const uint32_t off = row * 64 + ((kca ^ asw) << 4);
                uint32_t ah[4], al[4];
                ldm_x4(ah[0], ah[1], ah[2], ah[3], sb + AH + off);
                ldm_x4(al[0], al[1], al[2], al[3], sb + AL + off);
#pragma unroll
                for (int nf = 0; nf < 4; nf++) {
                    uint32_t* bhp = &bh[nf >> 1][(nf & 1) * 2];
                    uint32_t* blp = &bl[nf >> 1][(nf & 1) * 2];
                    mma_bf16(acc[mf][nf], ah, bhp);
                    mma_bf16(acc[mf][nf], ah, blp);
                    mma_bf16(acc[mf][nf], al, bhp);
                }
            }
        }
    }

    // ---- epilogue ----
#pragma unroll
    for (int mf = 0; mf < 4; mf++) {
#pragma unroll
        for (int nf = 0; nf < 4; nf++) {
            const int r0 = bm + wm * 64 + mf * 16 + (lane >> 2);
            const int cc = bn + wn * 32 + nf * 8 + (lane & 3) * 2;
#pragma unroll
            for (int half = 0; half < 2; half++) {
                const int m = r0 + half * 8;
                float2 v = make_float2(acc[mf][nf][half * 2],
                                       acc[mf][nf][half * 2 + 1]);
                if (EPI == 1) {
                    const float2 r = *(const float2*)&res[(size_t)m * N + cc];
                    v.x += r.x; v.y += r.y;
                }
                if (EPI == 2) {
                    const float2 bb = *(const float2*)&bias[cc];
                    v.x += bb.x; v.y += bb.y;
                    v.x = 0.5f * v.x * (1.f + erff(v.x * 0.70710678118654752f));
                    v.y = 0.5f * v.y * (1.f + erff(v.y * 0.70710678118654752f));
                }
                if (EPI == 3) {
                    const float2 bb = *(const float2*)&bias[cc];
                    const float2 r = *(const float2*)&res[(size_t)m * N + cc];
                    v.x += bb.x + r.x; v.y += bb.y + r.y;
                }
                if (EPI == 4) {
                    const float a = v.x * scale, b = v.y * scale;
                    float la, lb;
                    const uint32_t h = pack_hi(a, b, la, lb);
                    *(uint32_t*)&Oh[(size_t)m * N + cc] = h;
                    *(uint32_t*)&Ol[(size_t)m * N + cc] = pack_bf(la, lb);
                } else {
                    *(float2*)&C[(size_t)m * N + cc] = v;
                }
            }
        }
    }
}

// ============ HMMA bf16x3 flash attention, cp.async double-buffered ========
// CTA: 128 query rows of one (b,h). 8 warps x 16-row tiles. 64-key chunks.
// smem: 2 stages x {KH,KL,VH,VL 8KB each} = 64KB + mask 2x64 floats
__global__ __launch_bounds__(256) void attn_mma2(
    const __nv_bfloat16* __restrict__ Qh_g, const __nv_bfloat16* __restrict__ Ql_g,
    const __nv_bfloat16* __restrict__ Kh_g, const __nv_bfloat16* __restrict__ Kl_g,
    const __nv_bfloat16* __restrict__ Vh_g, const __nv_bfloat16* __restrict__ Vl_g,
    const int* __restrict__ mask, float* __restrict__ O)
{
    extern __shared__ __align__(16) uint8_t sm[];
    const uint32_t sb = smem_u32(sm);
    const uint32_t STG = 32768;          // per-stage size
    const uint32_t KHo = 0, KLo = 8192, VHo = 16384, VLo = 24576;
    float* mbuf = (float*)(sm + 65536);  // [2][64]

    const int tid = threadIdx.x;
    const int lane = tid & 31;
    const int warp = tid >> 5;
    const int bh = blockIdx.x;
    const int b = bh / HH, h = bh % HH;
    const int bm = blockIdx.y * 128;

    // ---- stage Q hi/lo into stage0 area, ldmatrix to regs ----
#pragma unroll
    for (int i = 0; i < 4; i++) {
        const int slot = tid + i * 256;    // 128 rows x 8 chunks
        const int r = slot >> 3, ch = slot & 7;
        const size_t gq = (size_t)(b * SS + bm + r) * DD + h * DKK + ch * 8;
        const uint32_t off = offsw((uint32_t)r, (uint32_t)ch);
        *(uint4*)(sm + off)         = *(const uint4*)&Qh_g[gq];
        *(uint4*)(sm + 16384 + off) = *(const uint4*)&Ql_g[gq];
    }
    __syncthreads();

    const int arow = lane & 15;
    const int akc  = lane >> 4;
    uint32_t Qh[4][4], Ql[4][4];
    {
        const uint32_t row = (uint32_t)(warp * 16 + arow);
#pragma unroll
        for (int kc = 0; kc < 4; kc++) {
            const uint32_t off = offsw(row, (uint32_t)(kc * 2 + akc));
            ldm_x4(Qh[kc][0], Qh[kc][1], Qh[kc][2], Qh[kc][3], sb + off);
            ldm_x4(Ql[kc][0], Ql[kc][1], Ql[kc][2], Ql[kc][3], sb + 16384 + off);
        }
    }
    __syncthreads();

    const int brow = ((lane >> 4) << 3) + (lane & 7);
    const int bkc  = (lane >> 3) & 1;
    const int vkey = lane & 15;
    const int vch  = lane >> 4;

    // cp.async slot addressing (2 slots/thread per buffer)
    const int s0r = tid >> 3, s0c = tid & 7;
    const int s1r = (tid + 256) >> 3, s1c = tid & 7;  // slot+256: row += 32, same chunk
    const uint32_t off0 = offsw((uint32_t)s0r, (uint32_t)s0c);
    const uint32_t off1 = offsw((uint32_t)s1r, (uint32_t)s1c);

    // prologue: issue chunk 0 into stage 0
    {
        const size_t g0 = (size_t)(b * SS + s0r) * DD + h * DKK + s0c * 8;
        const size_t g1 = (size_t)(b * SS + s1r) * DD + h * DKK + s1c * 8;
        cpa16(sb + KHo + off0, Kh_g + g0); cpa16(sb + KHo + off1, Kh_g + g1);
        cpa16(sb + KLo + off0, Kl_g + g0); cpa16(sb + KLo + off1, Kl_g + g1);
        cpa16(sb + VHo + off0, Vh_g + g0); cpa16(sb + VHo + off1, Vh_g + g1);
        cpa16(sb + VLo + off0, Vl_g + g0); cpa16(sb + VLo + off1, Vl_g + g1);
        asm volatile("cp.async.commit_group;" ::: "memory");
    }
    int mreg = (tid < 64) ? mask[b * SS + tid] : 1;

    float S[8][4], Ofr[8][4];
#pragma unroll
    for (int nf = 0; nf < 8; nf++)
#pragma unroll
        for (int e = 0; e < 4; e++) Ofr[nf][e] = 0.f;
    float m0 = -1e30f, m1 = -1e30f, l0 = 0.f, l1 = 0.f;

    const int nchunk = SS / 64;   // 32
    for (int t = 0; t < nchunk; t++) {
        const int s = t & 1;
        const uint32_t base = sb + (uint32_t)s * STG;
        int mnext = 1;

        if (t + 1 < nchunk) {
            const uint32_t nb = sb + (uint32_t)(s ^ 1) * STG;
            const int nt0 = (t + 1) * 64;
            const size_t g0 = (size_t)(b * SS + nt0 + s0r) * DD + h * DKK + s0c * 8;
            const size_t g1 = (size_t)(b * SS + nt0 + s1r) * DD + h * DKK + s1c * 8;
            cpa16(nb + KHo + off0, Kh_g + g0); cpa16(nb + KHo + off1, Kh_g + g1);
            cpa16(nb + KLo + off0, Kl_g + g0); cpa16(nb + KLo + off1, Kl_g + g1);
            cpa16(nb + VHo + off0, Vh_g + g0); cpa16(nb + VHo + off1, Vh_g + g1);
            cpa16(nb + VLo + off0, Vl_g + g0); cpa16(nb + VLo + off1, Vl_g + g1);
            asm volatile("cp.async.commit_group;" ::: "memory");
            if (tid < 64) mnext = mask[b * SS + nt0 + tid];
            asm volatile("cp.async.wait_group 1;" ::: "memory");
        } else {
            asm volatile("cp.async.wait_group 0;" ::: "memory");
        }
        if (tid < 64) mbuf[s * 64 + tid] = mreg ? 0.f : -100.f;
        __syncthreads();

        // ---- S = Q K^T (bf16x3) ----
#pragma unroll
        for (int nf = 0; nf < 8; nf++)
#pragma unroll
            for (int e = 0; e < 4; e++) S[nf][e] = 0.f;

#pragma unroll
        for (int p = 0; p < 4; p++) {
#pragma unroll
            for (int kc = 0; kc < 4; kc++) {
                const uint32_t row = (uint32_t)(p * 16 + brow);
                const uint32_t off = offsw(row, (uint32_t)(kc * 2 + bkc));
                uint32_t kh[4], kl[4];
                ldm_x4(kh[0], kh[1], kh[2], kh[3], base + KHo + off);
                ldm_x4(kl[0], kl[1], kl[2], kl[3], base + KLo + off);
                mma_bf16(S[p * 2],     Qh[kc], &kh[0]);
                mma_bf16(S[p * 2 + 1], Qh[kc], &kh[2]);
                mma_bf16(S[p * 2],     Qh[kc], &kl[0]);
                mma_bf16(S[p * 2 + 1], Qh[kc], &kl[2]);
                mma_bf16(S[p * 2],     Ql[kc], &kh[0]);
                mma_bf16(S[p * 2 + 1], Ql[kc], &kh[2]);
            }
        }

        // ---- mask + online softmax ----
        float cm0 = -1e30f, cm1 = -1e30f;
#pragma unroll
        for (int nf = 0; nf < 8; nf++) {
            const float2 mv = *(const float2*)&mbuf[s * 64 + nf * 8 + (lane & 3) * 2];
            S[nf][0] += mv.x; S[nf][1] += mv.y;
            S[nf][2] += mv.x; S[nf][3] += mv.y;
            cm0 = fmaxf(cm0, fmaxf(S[nf][0], S[nf][1]));
            cm1 = fmaxf(cm1, fmaxf(S[nf][2], S[nf][3]));
        }
        cm0 = fmaxf(cm0, __shfl_xor_sync(0xffffffffu, cm0, 1));
        cm0 = fmaxf(cm0, __shfl_xor_sync(0xffffffffu, cm0, 2));
        cm1 = fmaxf(cm1, __shfl_xor_sync(0xffffffffu, cm1, 1));
        cm1 = fmaxf(cm1, __shfl_xor_sync(0xffffffffu, cm1, 2));

        const float mn0 = fmaxf(m0, cm0);
        const float mn1 = fmaxf(m1, cm1);
        const float c0 = __expf(m0 - mn0);
        const float c1 = __expf(m1 - mn1);
        m0 = mn0; m1 = mn1;
        l0 *= c0; l1 *= c1;
#pragma unroll
        for (int nf = 0; nf < 8; nf++) {
            Ofr[nf][0] *= c0; Ofr[nf][1] *= c0;
            Ofr[nf][2] *= c1; Ofr[nf][3] *= c1;
        }
#pragma unroll
        for (int nf = 0; nf < 8; nf++) {
            S[nf][0] = __expf(S[nf][0] - mn0);
            S[nf][1] = __expf(S[nf][1] - mn0);
            S[nf][2] = __expf(S[nf][2] - mn1);
            S[nf][3] = __expf(S[nf][3] - mn1);
            l0 += S[nf][0] + S[nf][1];
            l1 += S[nf][2] + S[nf][3];
        }

        // ---- O += P V (bf16x3) ----
#pragma unroll
        for (int kcp = 0; kcp < 4; kcp++) {
            uint32_t Ah[4], Al[4];
            float ra, rb;
            Ah[0] = pack_hi(S[kcp * 2][0],     S[kcp * 2][1],     ra, rb); Al[0] = pack_bf(ra, rb);
            Ah[1] = pack_hi(S[kcp * 2][2],     S[kcp * 2][3],     ra, rb); Al[1] = pack_bf(ra, rb);
            Ah[2] = pack_hi(S[kcp * 2 + 1][0], S[kcp * 2 + 1][1], ra, rb); Al[2] = pack_bf(ra, rb);
            Ah[3] = pack_hi(S[kcp * 2 + 1][2], S[kcp * 2 + 1][3], ra, rb); Al[3] = pack_bf(ra, rb);
#pragma unroll
            for (int vv = 0; vv < 4; vv++) {
                const uint32_t off = offsw((uint32_t)(kcp * 16 + vkey),
                                           (uint32_t)(vv * 2 + vch));
                uint32_t vh[4], vl[4];
                ldm_x4_t(vh[0], vh[1], vh[2], vh[3], base + VHo + off);
                ldm_x4_t(vl[0], vl[1], vl[2], vl[3], base + VLo + off);
                mma_bf16(Ofr[vv * 2],     Ah, &vh[0]);
                mma_bf16(Ofr[vv * 2 + 1], Ah, &vh[2]);
                mma_bf16(Ofr[vv * 2],     Ah, &vl[0]);
                mma_bf16(Ofr[vv * 2 + 1], Ah, &vl[2]);
                mma_bf16(Ofr[vv * 2],     Al, &vh[0]);
                mma_bf16(Ofr[vv * 2 + 1], Al, &vh[2]);
            }
        }
        __syncthreads();
        mreg = mnext;
    }

    // ---- finalize ----
    l0 += __shfl_xor_sync(0xffffffffu, l0, 1);
    l0 += __shfl_xor_sync(0xffffffffu, l0, 2);
    l1 += __shfl_xor_sync(0xffffffffu, l1, 1);
    l1 += __shfl_xor_sync(0xffffffffu, l1, 2);
    const float i0 = 1.f / l0, i1 = 1.f / l1;

    const int r0 = b * SS + bm + warp * 16 + (lane >> 2);
#pragma unroll
    for (int nf = 0; nf < 8; nf++) {
        const int col = h * DKK + nf * 8 + (lane & 3) * 2;
        *(float2*)&O[(size_t)r0 * DD + col] =
            make_float2(Ofr[nf][0] * i0, Ofr[nf][1] * i0);
        *(float2*)&O[(size_t)(r0 + 8) * DD + col] =
            make_float2(Ofr[nf][2] * i1, Ofr[nf][3] * i1);
    }
}

// ---------------- layernorm over last dim (D=512), one block per row -------
__global__ __launch_bounds__(256) void layernorm_k(
    const float* __restrict__ in, const float* __restrict__ gamma,
    const float* __restrict__ beta, float* __restrict__ out)
{
    const int row = blockIdx.x;
    const int tid = threadIdx.x;
    const float* xr = in + (size_t)row * DD;

    const float x0 = xr[tid];
    const float x1 = xr[tid + 256];

    __shared__ float wsum[8];
    __shared__ float sval;

    float s = x0 + x1;
#pragma unroll
    for (int off = 16; off; off >>= 1) s += __shfl_xor_sync(0xffffffffu, s, off);
    if ((tid & 31) == 0) wsum[tid >> 5] = s;
    __syncthreads();
    if (tid == 0) {
        float t = 0.f;
#pragma unroll
        for (int i = 0; i < 8; i++) t += wsum[i];
        sval = t * (1.f / DD);
    }
    __syncthreads();
    const float mu = sval;
    __syncthreads();

    const float d0 = x0 - mu, d1 = x1 - mu;
    s = d0 * d0 + d1 * d1;
#pragma unroll
    for (int off = 16; off; off >>= 1) s += __shfl_xor_sync(0xffffffffu, s, off);
    if ((tid & 31) == 0) wsum[tid >> 5] = s;
    __syncthreads();
    if (tid == 0) {
        float t = 0.f;
#pragma unroll
        for (int i = 0; i < 8; i++) t += wsum[i];
        sval = rsqrtf(t * (1.f / DD) + 1e-5f);
    }
    __syncthreads();
    const float rstd = sval;

    out[(size_t)row * DD + tid]       = d0 * rstd * gamma[tid] + beta[tid];
    out[(size_t)row * DD + tid + 256] = d1 * rstd * gamma[tid + 256] + beta[tid + 256];
}

// ---------------- launch --------------------------------------------------
extern "C" void kernel_launch(void* const* d_in, const int* in_sizes, int n_in,
                              void* d_out, int out_size)
{
    const float* x    = (const float*)d_in[0];
    const int*   mask = (const int*)d_in[1];
    const float* Wq   = (const float*)d_in[2];
    const float* Wk   = (const float*)d_in[3];
    const float* Wv   = (const float*)d_in[4];
    const float* Wp   = (const float*)d_in[5];
    const float* W1   = (const float*)d_in[6];
    const float* b1   = (const float*)d_in[7];
    const float* W2   = (const float*)d_in[8];
    const float* b2   = (const float*)d_in[9];
    const float* ln1g = (const float*)d_in[10];
    const float* ln1b = (const float*)d_in[11];
    const float* ln2g = (const float*)d_in[12];
    const float* ln2b = (const float*)d_in[13];
    float* out = (float*)d_out;

    float *ctx, *attres, *h, *ff;
    __nv_bfloat16 *wqkvh, *wqkvl, *wph, *wpl, *w1h, *w1l, *w2h, *w2l, *qkvh, *qkvl;
    cudaGetSymbolAddress((void**)&ctx,    g_ctx);
    cudaGetSymbolAddress((void**)&attres, g_attres);
    cudaGetSymbolAddress((void**)&h,      g_h);
    cudaGetSymbolAddress((void**)&ff,     g_ff);
    cudaGetSymbolAddress((void**)&wqkvh,  g_wqkvh);
    cudaGetSymbolAddress((void**)&wqkvl,  g_wqkvl);
    cudaGetSymbolAddress((void**)&wph,    g_wph);
    cudaGetSymbolAddress((void**)&wpl,    g_wpl);
    cudaGetSymbolAddress((void**)&w1h,    g_w1h);
    cudaGetSymbolAddress((void**)&w1l,    g_w1l);
    cudaGetSymbolAddress((void**)&w2h,    g_w2h);
    cudaGetSymbolAddress((void**)&w2l,    g_w2l);
    cudaGetSymbolAddress((void**)&qkvh,   g_qkvh);
    cudaGetSymbolAddress((void**)&qkvl,   g_qkvl);

    cudaFuncSetAttribute(attn_mma2, cudaFuncAttributeMaxDynamicSharedMemorySize, 66048);

    // weight prep (fp32 -> bf16 hi/lo)
    prep_w<<<256, 256>>>(Wq, wqkvh, wqkvl);
    prep_w<<<256, 256>>>(Wk, wqkvh + DD * DD, wqkvl + DD * DD);
    prep_w<<<256, 256>>>(Wv, wqkvh + 2 * DD * DD, wqkvl + 2 * DD * DD);
    prep_w<<<256, 256>>>(Wp, wph, wpl);
    prep_w<<<1024, 256>>>(W1, w1h, w1l);
    prep_w<<<1024, 256>>>(W2, w2h, w2l);

    // fused QKV projection -> bf16 hi/lo (q scaled by 1/8)
    gemm_h2<4><<<dim3(DD / 128, MROWS / 128, 3), 256>>>(
        x, wqkvh, wqkvl, nullptr, nullptr, nullptr, qkvh, qkvl, MROWS, DD, DD);

    // attention (tensor-core flash, cp.async pipelined)
    attn_mma2<<<dim3(BB * HH, SS / 128), 256, 66048>>>(
        qkvh, qkvl,
        qkvh + (size_t)MROWS * DD, qkvl + (size_t)MROWS * DD,
        qkvh + 2 * (size_t)MROWS * DD, qkvl + 2 * (size_t)MROWS * DD,
        mask, ctx);

    // output projection + residual, LN1
    gemm_h2<1><<<dim3(DD / 128, MROWS / 128), 256>>>(
        ctx, wph, wpl, nullptr, x, attres, nullptr, nullptr, MROWS, DD, DD);
    layernorm_k<<<MROWS, 256>>>(attres, ln1g, ln1b, h);

    // FFN
    gemm_h2<2><<<dim3(DFF / 128, MROWS / 128), 256>>>(
        h, w1h, w1l, b1, nullptr, ff, nullptr, nullptr, MROWS, DFF, DD);
    gemm_h2<3><<<dim3(DD / 128, MROWS / 128), 256>>>(
        ff, w2h, w2l, b2, h, attres, nullptr, nullptr, MROWS, DD, DFF);
    layernorm_k<<<MROWS, 256>>>(attres, ln2g, ln2b, out);
}

// round 16
// speedup vs baseline: 1.0459x; 1.0459x over previous
#include <cuda_runtime.h>
#include <cuda_bf16.h>
#include <math.h>
#include <stdint.h>

#define BB 4
#define SS 2048
#define DD 512
#define HH 8
#define DKK 64
#define DFF 2048
#define MROWS (BB * SS)   // 8192

// ---------------- scratch (static device globals; no allocations) ----------
__device__ float g_ctx[MROWS * DD];
__device__ float g_attres[MROWS * DD];
__device__ float g_h[MROWS * DD];
__device__ float g_ff[MROWS * DFF];
// bf16 hi/lo weights
__device__ __nv_bfloat16 g_wqkvh[3 * DD * DD];
__device__ __nv_bfloat16 g_wqkvl[3 * DD * DD];
__device__ __nv_bfloat16 g_wph[DD * DD];
__device__ __nv_bfloat16 g_wpl[DD * DD];
__device__ __nv_bfloat16 g_w1h[DFF * DD];
__device__ __nv_bfloat16 g_w1l[DFF * DD];
__device__ __nv_bfloat16 g_w2h[DD * DFF];
__device__ __nv_bfloat16 g_w2l[DD * DFF];
// bf16 hi/lo activations (q,k,v stacked)
__device__ __nv_bfloat16 g_qkvh[3 * MROWS * DD];
__device__ __nv_bfloat16 g_qkvl[3 * MROWS * DD];

// ================= helpers =================================================
__device__ __forceinline__ uint32_t smem_u32(const void* p) {
    uint32_t a;
    asm("{ .reg .u64 t; cvta.to.shared.u64 t, %1; cvt.u32.u64 %0, t; }"
        : "=r"(a) : "l"(p));
    return a;
}
__device__ __forceinline__ void ldm_x4(uint32_t& r0, uint32_t& r1,
                                       uint32_t& r2, uint32_t& r3, uint32_t addr) {
    asm volatile("ldmatrix.sync.aligned.m8n8.x4.shared.b16 {%0,%1,%2,%3}, [%4];"
                 : "=r"(r0), "=r"(r1), "=r"(r2), "=r"(r3) : "r"(addr));
}
__device__ __forceinline__ void ldm_x4_t(uint32_t& r0, uint32_t& r1,
                                         uint32_t& r2, uint32_t& r3, uint32_t addr) {
    asm volatile("ldmatrix.sync.aligned.m8n8.x4.trans.shared.b16 {%0,%1,%2,%3}, [%4];"
                 : "=r"(r0), "=r"(r1), "=r"(r2), "=r"(r3) : "r"(addr));
}
__device__ __forceinline__ void mma_bf16(float* d, const uint32_t* a,
                                         const uint32_t* b) {
    asm volatile(
        "mma.sync.aligned.m16n8k16.row.col.f32.bf16.bf16.f32 "
        "{%0,%1,%2,%3}, {%4,%5,%6,%7}, {%8,%9}, {%0,%1,%2,%3};"
        : "+f"(d[0]), "+f"(d[1]), "+f"(d[2]), "+f"(d[3])
        : "r"(a[0]), "r"(a[1]), "r"(a[2]), "r"(a[3]), "r"(b[0]), "r"(b[1]));
}
__device__ __forceinline__ uint32_t pack_hi(float a, float b, float& la, float& lb) {
    __nv_bfloat162 h = __floats2bfloat162_rn(a, b);
    la = a - __bfloat162float(h.x);
    lb = b - __bfloat162float(h.y);
    union { __nv_bfloat162 v; uint32_t u; } cv; cv.v = h;
    return cv.u;
}
__device__ __forceinline__ uint32_t pack_bf(float a, float b) {
    __nv_bfloat162 h = __floats2bfloat162_rn(a, b);
    union { __nv_bfloat162 v; uint32_t u; } cv; cv.v = h;
    return cv.u;
}
// 128B-row swizzle (8 x 16B chunks)
__device__ __forceinline__ uint32_t offsw(uint32_t row, uint32_t chunk) {
    return row * 128u + ((chunk ^ (row & 7u)) << 4);
}

// ---------------- fused weight prep: fp32 -> bf16 hi/lo, 1 launch ----------
__global__ __launch_bounds__(256) void prep_all(
    const float* __restrict__ wq, const float* __restrict__ wk,
    const float* __restrict__ wv, const float* __restrict__ wp,
    const float* __restrict__ w1, const float* __restrict__ w2)
{
    const int sel = blockIdx.y;
    const float* s;
    __nv_bfloat16 *hi, *lo;
    int n4;                      // number of float4 elements
    switch (sel) {
        case 0:  s = wq; hi = g_wqkvh;               lo = g_wqkvl;               n4 = DD * DD / 4;  break;
        case 1:  s = wk; hi = g_wqkvh + DD * DD;     lo = g_wqkvl + DD * DD;     n4 = DD * DD / 4;  break;
        case 2:  s = wv; hi = g_wqkvh + 2 * DD * DD; lo = g_wqkvl + 2 * DD * DD; n4 = DD * DD / 4;  break;
        case 3:  s = wp; hi = g_wph;                 lo = g_wpl;                 n4 = DD * DD / 4;  break;
        case 4:  s = w1; hi = g_w1h;                 lo = g_w1l;                 n4 = DFF * DD / 4; break;
        default: s = w2; hi = g_w2h;                 lo = g_w2l;                 n4 = DD * DFF / 4; break;
    }
    const int i = blockIdx.x * 256 + threadIdx.x;
    if (i >= n4) return;
    const float4 f = *(const float4*)&s[(size_t)i * 4];
    float la, lb, lc, ld;
    uint32_t h0 = pack_hi(f.x, f.y, la, lb);
    uint32_t h1 = pack_hi(f.z, f.w, lc, ld);
    *(uint2*)&hi[(size_t)i * 4] = make_uint2(h0, h1);
    *(uint2*)&lo[(size_t)i * 4] = make_uint2(pack_bf(la, lb), pack_bf(lc, ld));
}

// ============ HMMA bf16x3 GEMM: C[m,n] = sum_k A[m,k]*W[n,k] ===============
// A fp32 (cvt in kernel); B pre-split bf16 hi/lo. 128x128 tile, BK=32, 8 warps.
// EPI: 1 +res, 2 +bias->GELU, 3 +bias+res, 4 write bf16 hi/lo (QKV, z-indexed)
template <int EPI>
__global__ __launch_bounds__(256, 2) void gemm_p(
    const float* __restrict__ A,
    const __nv_bfloat16* __restrict__ Bh_, const __nv_bfloat16* __restrict__ Bl_,
    const float* __restrict__ bias, const float* __restrict__ res,
    float* __restrict__ C,
    __nv_bfloat16* __restrict__ Oh_, __nv_bfloat16* __restrict__ Ol_,
    int M, int N, int K)
{
    __shared__ __align__(16) uint8_t sm[32768];
    const uint32_t sb = smem_u32(sm);
    const uint32_t AH = 0, AL = 8192, BH = 16384, BL = 24576;

    const int tid = threadIdx.x;
    const int lane = tid & 31;
    const int warp = tid >> 5;
    const int wm = warp >> 2;
    const int wn = warp & 3;
    const int bm = blockIdx.y * 128;
    const int bn = blockIdx.x * 128;

    const __nv_bfloat16* Bh = Bh_;
    const __nv_bfloat16* Bl = Bl_;
    __nv_bfloat16* Oh = Oh_;
    __nv_bfloat16* Ol = Ol_;
    float scale = 1.f;
    if (EPI == 4) {
        const int z = blockIdx.z;
        Bh += (size_t)z * N * K; Bl += (size_t)z * N * K;
        Oh += (size_t)z * M * N; Ol += (size_t)z * M * N;
        if (z == 0) scale = 0.125f;
    }

    float acc[4][4][4];
#pragma unroll
    for (int i = 0; i < 4; i++)
#pragma unroll
        for (int j = 0; j < 4; j++)
#pragma unroll
            for (int e = 0; e < 4; e++) acc[i][j][e] = 0.f;

    const int arow = lane & 15;
    const int akc  = lane >> 4;
    const int brow = ((lane >> 4) << 3) + (lane & 7);
    const int bkc  = (lane >> 3) & 1;
    const uint32_t asw = (uint32_t)(arow & 3);
    const uint32_t bsw = (uint32_t)(brow & 3);

    const int nslab = K >> 5;
    for (int t = 0; t < nslab; t++) {
        const int k0 = t << 5;

        // ---- load slab: A fp32, B bf16 hi/lo ----
        float4 av[4];
        uint4 bhv[2], blv[2];
#pragma unroll
        for (int i = 0; i < 4; i++) {
            const int idx = tid + i * 256;
            const int r = idx >> 3, c4 = idx & 7;
            av[i] = *(const float4*)&A[(size_t)(bm + r) * K + k0 + c4 * 4];
        }
#pragma unroll
        for (int i = 0; i < 2; i++) {
            const int slot = tid + i * 256;      // 0..511 = 128 rows x 4 chunks
            const int r = slot >> 2, ch = slot & 3;
            bhv[i] = *(const uint4*)&Bh[(size_t)(bn + r) * K + k0 + ch * 8];
            blv[i] = *(const uint4*)&Bl[(size_t)(bn + r) * K + k0 + ch * 8];
        }
        __syncthreads();   // previous slab's mma reads done

        // ---- convert A + store; store B raw ----
#pragma unroll
        for (int i = 0; i < 4; i++) {
            const int idx = tid + i * 256;
            const int r = idx >> 3, c4 = idx & 7;
            const uint32_t chunk = (uint32_t)(c4 >> 1);
            const uint32_t off = (uint32_t)r * 64 +
                                 ((chunk ^ (uint32_t)(r & 3)) << 4) + (c4 & 1) * 8;
            float lx, ly, lz, lw;
            uint32_t h0 = pack_hi(av[i].x, av[i].y, lx, ly);
            uint32_t h1 = pack_hi(av[i].z, av[i].w, lz, lw);
            *(uint2*)(sm + AH + off) = make_uint2(h0, h1);
            *(uint2*)(sm + AL + off) = make_uint2(pack_bf(lx, ly), pack_bf(lz, lw));
        }
#pragma unroll
        for (int i = 0; i < 2; i++) {
            const int slot = tid + i * 256;
            const int r = slot >> 2, ch = slot & 3;
            const uint32_t off = (uint32_t)r * 64 +
                                 (((uint32_t)ch ^ (uint32_t)(r & 3)) << 4);
            *(uint4*)(sm + BH + off) = bhv[i];
            *(uint4*)(sm + BL + off) = blv[i];
        }
        __syncthreads();

        // ---- mma phase: 2 k-steps of 16 ----
#pragma unroll
        for (int ks = 0; ks < 2; ks++) {
            const uint32_t kca = (uint32_t)(ks * 2 + akc);
            const uint32_t kcb = (uint32_t)(ks * 2 + bkc);

            uint32_t bh[2][4], bl[2][4];
#pragma unroll
            for (int p = 0; p < 2; p++) {
                const uint32_t row = (uint32_t)(wn * 32 + p * 16 + brow);
                const uint32_t off = row * 64 + ((kcb ^ bsw) << 4);
                ldm_x4(bh[p][0], bh[p][1], bh[p][2], bh[p][3], sb + BH + off);
                ldm_x4(bl[p][0], bl[p][1], bl[p][2], bl[p][3], sb + BL + off);
            }
#pragma unroll
            for (int mf = 0; mf < 4; mf++) {
                const uint32_t row = (uint32_t)(wm * 64 + mf * 16 + arow);
                const uint32_t off = row * 64 + ((kca ^ asw) << 4);
                uint32_t ah[4], al[4];
                ldm_x4(ah[0], ah[1], ah[2], ah[3], sb + AH + off);
                ldm_x4(al[0], al[1], al[2], al[3], sb + AL + off);
#pragma unroll
                for (int nf = 0; nf < 4; nf++) {
                    uint32_t* bhp = &bh[nf >> 1][(nf & 1) * 2];
                    uint32_t* blp = &bl[nf >> 1][(nf & 1) * 2];
                    mma_bf16(acc[mf][nf], ah, bhp);
                    mma_bf16(acc[mf][nf], ah, blp);
                    mma_bf16(acc[mf][nf], al, bhp);
                }
            }
        }
    }

    // ---- epilogue ----
#pragma unroll
    for (int mf = 0; mf < 4; mf++) {
#pragma unroll
        for (int nf = 0; nf < 4; nf++) {
            const int r0 = bm + wm * 64 + mf * 16 + (lane >> 2);
            const int cc = bn + wn * 32 + nf * 8 + (lane & 3) * 2;
#pragma unroll
            for (int half = 0; half < 2; half++) {
                const int m = r0 + half * 8;
                float2 v = make_float2(acc[mf][nf][half * 2],
                                       acc[mf][nf][half * 2 + 1]);
                if (EPI == 1) {
                    const float2 r = *(const float2*)&res[(size_t)m * N + cc];
                    v.x += r.x; v.y += r.y;
                }
                if (EPI == 2) {
                    const float2 bb = *(const float2*)&bias[cc];
                    v.x += bb.x; v.y += bb.y;
                    v.x = 0.5f * v.x * (1.f + erff(v.x * 0.70710678118654752f));
                    v.y = 0.5f * v.y * (1.f + erff(v.y * 0.70710678118654752f));
                }
                if (EPI == 3) {
                    const float2 bb = *(const float2*)&bias[cc];
                    const float2 r = *(const float2*)&res[(size_t)m * N + cc];
                    v.x += bb.x + r.x; v.y += bb.y + r.y;
                }
                if (EPI == 4) {
                    const float a = v.x * scale, b = v.y * scale;
                    float la, lb;
                    const uint32_t hh = pack_hi(a, b, la, lb);
                    *(uint32_t*)&Oh[(size_t)m * N + cc] = hh;
                    *(uint32_t*)&Ol[(size_t)m * N + cc] = pack_bf(la, lb);
                } else {
                    *(float2*)&C[(size_t)m * N + cc] = v;
                }
            }
        }
    }
}

// ============ HMMA bf16x3 flash attention (pre-split bf16 inputs) ==========
// CTA: 128 query rows of one (b,h). 8 warps x 16-row tiles. 64-key chunks.
__global__ __launch_bounds__(256) void attn_b(
    const __nv_bfloat16* __restrict__ Qh_g, const __nv_bfloat16* __restrict__ Ql_g,
    const __nv_bfloat16* __restrict__ Kh_g, const __nv_bfloat16* __restrict__ Kl_g,
    const __nv_bfloat16* __restrict__ Vh_g, const __nv_bfloat16* __restrict__ Vl_g,
    const int* __restrict__ mask, float* __restrict__ O)
{
    __shared__ __align__(16) uint8_t sm[32768 + 256];
    const uint32_t sb = smem_u32(sm);
    const uint32_t KH = 0, KL = 8192, VH = 16384, VL = 24576, MB = 32768;
    float* mbf = (float*)(sm + MB);

    const int tid = threadIdx.x;
    const int lane = tid & 31;
    const int warp = tid >> 5;
    const int bh = blockIdx.x;
    const int b = bh / HH, h = bh % HH;
    const int bm = blockIdx.y * 128;

    // ---- stage Q hi/lo (raw copy), ldmatrix to regs ----
#pragma unroll
    for (int i = 0; i < 4; i++) {
        const int slot = tid + i * 256;        // 0..1023 = 128 rows x 8 chunks
        const int r = slot >> 3, ch = slot & 7;
        const size_t gq = (size_t)(b * SS + bm + r) * DD + h * DKK + ch * 8;
        const uint32_t off = offsw((uint32_t)r, (uint32_t)ch);
        *(uint4*)(sm + off)         = *(const uint4*)&Qh_g[gq];
        *(uint4*)(sm + 16384 + off) = *(const uint4*)&Ql_g[gq];
    }
    __syncthreads();

    const int arow = lane & 15;
    const int akc  = lane >> 4;
    uint32_t Qh[4][4], Ql[4][4];
    {
        const uint32_t row = (uint32_t)(warp * 16 + arow);
#pragma unroll
        for (int kc = 0; kc < 4; kc++) {
            const uint32_t off = offsw(row, (uint32_t)(kc * 2 + akc));
            ldm_x4(Qh[kc][0], Qh[kc][1], Qh[kc][2], Qh[kc][3], sb + off);
            ldm_x4(Ql[kc][0], Ql[kc][1], Ql[kc][2], Ql[kc][3], sb + 16384 + off);
        }
    }
    __syncthreads();

    const int brow = ((lane >> 4) << 3) + (lane & 7);
    const int bkc  = (lane >> 3) & 1;
    const int vkey = lane & 15;
    const int vch  = lane >> 4;

    float S[8][4], Ofr[8][4];
#pragma unroll
    for (int nf = 0; nf < 8; nf++)
#pragma unroll
        for (int e = 0; e < 4; e++) Ofr[nf][e] = 0.f;
    float m0 = -1e30f, m1 = -1e30f, l0 = 0.f, l1 = 0.f;

    for (int t0 = 0; t0 < SS; t0 += 64) {
        // ---- load K,V chunk (raw bf16 hi/lo copies) ----
#pragma unroll
        for (int i = 0; i < 2; i++) {
            const int slot = tid + i * 256;    // 0..511 = 64 rows x 8 chunks
            const int r = slot >> 3, ch = slot & 7;
            const size_t g = (size_t)(b * SS + t0 + r) * DD + h * DKK + ch * 8;
            const uint32_t off = offsw((uint32_t)r, (uint32_t)ch);
            *(uint4*)(sm + KH + off) = *(const uint4*)&Kh_g[g];
            *(uint4*)(sm + KL + off) = *(const uint4*)&Kl_g[g];
            *(uint4*)(sm + VH + off) = *(const uint4*)&Vh_g[g];
            *(uint4*)(sm + VL + off) = *(const uint4*)&Vl_g[g];
        }
        if (tid < 64) mbf[tid] = mask[b * SS + t0 + tid] ? 0.f : -100.f;
        __syncthreads();

        // ---- S = Q K^T (bf16x3) ----
#pragma unroll
        for (int nf = 0; nf < 8; nf++)
#pragma unroll
            for (int e = 0; e < 4; e++) S[nf][e] = 0.f;

#pragma unroll
        for (int p = 0; p < 4; p++) {
#pragma unroll
            for (int kc = 0; kc < 4; kc++) {
                const uint32_t row = (uint32_t)(p * 16 + brow);
                const uint32_t off = offsw(row, (uint32_t)(kc * 2 + bkc));
                uint32_t kh[4], kl[4];
                ldm_x4(kh[0], kh[1], kh[2], kh[3], sb + KH + off);
                ldm_x4(kl[0], kl[1], kl[2], kl[3], sb + KL + off);
                mma_bf16(S[p * 2],     Qh[kc], &kh[0]);
                mma_bf16(S[p * 2 + 1], Qh[kc], &kh[2]);
                mma_bf16(S[p * 2],     Qh[kc], &kl[0]);
                mma_bf16(S[p * 2 + 1], Qh[kc], &kl[2]);
                mma_bf16(S[p * 2],     Ql[kc], &kh[0]);
                mma_bf16(S[p * 2 + 1], Ql[kc], &kh[2]);
            }
        }

        // ---- mask + online softmax ----
        float cm0 = -1e30f, cm1 = -1e30f;
#pragma unroll
        for (int nf = 0; nf < 8; nf++) {
            const float2 mv = *(const float2*)&mbf[nf * 8 + (lane & 3) * 2];
            S[nf][0] += mv.x; S[nf][1] += mv.y;
            S[nf][2] += mv.x; S[nf][3] += mv.y;
            cm0 = fmaxf(cm0, fmaxf(S[nf][0], S[nf][1]));
            cm1 = fmaxf(cm1, fmaxf(S[nf][2], S[nf][3]));
        }
        cm0 = fmaxf(cm0, __shfl_xor_sync(0xffffffffu, cm0, 1));
        cm0 = fmaxf(cm0, __shfl_xor_sync(0xffffffffu, cm0, 2));
        cm1 = fmaxf(cm1, __shfl_xor_sync(0xffffffffu, cm1, 1));
        cm1 = fmaxf(cm1, __shfl_xor_sync(0xffffffffu, cm1, 2));

        const float mn0 = fmaxf(m0, cm0);
        const float mn1 = fmaxf(m1, cm1);
        const float c0 = __expf(m0 - mn0);
        const float c1 = __expf(m1 - mn1);
        m0 = mn0; m1 = mn1;
        l0 *= c0; l1 *= c1;
#pragma unroll
        for (int nf = 0; nf < 8; nf++) {
            Ofr[nf][0] *= c0; Ofr[nf][1] *= c0;
            Ofr[nf][2] *= c1; Ofr[nf][3] *= c1;
        }
#pragma unroll
        for (int nf = 0; nf < 8; nf++) {
            S[nf][0] = __expf(S[nf][0] - mn0);
            S[nf][1] = __expf(S[nf][1] - mn0);
            S[nf][2] = __expf(S[nf][2] - mn1);
            S[nf][3] = __expf(S[nf][3] - mn1);
            l0 += S[nf][0] + S[nf][1];
            l1 += S[nf][2] + S[nf][3];
        }

        // ---- O += P V (bf16x3) ----
#pragma unroll
        for (int kcp = 0; kcp < 4; kcp++) {
            uint32_t Ah[4], Al[4];
            float ra, rb;
            Ah[0] = pack_hi(S[kcp * 2][0],     S[kcp * 2][1],     ra, rb); Al[0] = pack_bf(ra, rb);
            Ah[1] = pack_hi(S[kcp * 2][2],     S[kcp * 2][3],     ra, rb); Al[1] = pack_bf(ra, rb);
            Ah[2] = pack_hi(S[kcp * 2 + 1][0], S[kcp * 2 + 1][1], ra, rb); Al[2] = pack_bf(ra, rb);
            Ah[3] = pack_hi(S[kcp * 2 + 1][2], S[kcp * 2 + 1][3], ra, rb); Al[3] = pack_bf(ra, rb);
#pragma unroll
            for (int vv = 0; vv < 4; vv++) {
                const uint32_t off = offsw((uint32_t)(kcp * 16 + vkey),
                                           (uint32_t)(vv * 2 + vch));
                uint32_t vh[4], vl[4];
                ldm_x4_t(vh[0], vh[1], vh[2], vh[3], sb + VH + off);
                ldm_x4_t(vl[0], vl[1], vl[2], vl[3], sb + VL + off);
                mma_bf16(Ofr[vv * 2],     Ah, &vh[0]);
                mma_bf16(Ofr[vv * 2 + 1], Ah, &vh[2]);
                mma_bf16(Ofr[vv * 2],     Ah, &vl[0]);
                mma_bf16(Ofr[vv * 2 + 1], Ah, &vl[2]);
                mma_bf16(Ofr[vv * 2],     Al, &vh[0]);
                mma_bf16(Ofr[vv * 2 + 1], Al, &vh[2]);
            }
        }
        __syncthreads();
    }

    // ---- finalize ----
    l0 += __shfl_xor_sync(0xffffffffu, l0, 1);
    l0 += __shfl_xor_sync(0xffffffffu, l0, 2);
    l1 += __shfl_xor_sync(0xffffffffu, l1, 1);
    l1 += __shfl_xor_sync(0xffffffffu, l1, 2);
    const float i0 = 1.f / l0, i1 = 1.f / l1;

    const int r0 = b * SS + bm + warp * 16 + (lane >> 2);
#pragma unroll
    for (int nf = 0; nf < 8; nf++) {
        const int col = h * DKK + nf * 8 + (lane & 3) * 2;
        *(float2*)&O[(size_t)r0 * DD + col] =
            make_float2(Ofr[nf][0] * i0, Ofr[nf][1] * i0);
        *(float2*)&O[(size_t)(r0 + 8) * DD + col] =
            make_float2(Ofr[nf][2] * i1, Ofr[nf][3] * i1);
    }
}

// ---------------- layernorm over last dim (D=512), one block per row -------
__global__ __launch_bounds__(256) void layernorm_k(
    const float* __restrict__ in, const float* __restrict__ gamma,
    const float* __restrict__ beta, float* __restrict__ out)
{
    const int row = blockIdx.x;
    const int tid = threadIdx.x;
    const float* xr = in + (size_t)row * DD;

    const float x0 = xr[tid];
    const float x1 = xr[tid + 256];

    __shared__ float wsum[8];
    __shared__ float sval;

    float s = x0 + x1;
#pragma unroll
    for (int off = 16; off; off >>= 1) s += __shfl_xor_sync(0xffffffffu, s, off);
    if ((tid & 31) == 0) wsum[tid >> 5] = s;
    __syncthreads();
    if (tid == 0) {
        float t = 0.f;
#pragma unroll
        for (int i = 0; i < 8; i++) t += wsum[i];
        sval = t * (1.f / DD);
    }
    __syncthreads();
    const float mu = sval;
    __syncthreads();

    const float d0 = x0 - mu, d1 = x1 - mu;
    s = d0 * d0 + d1 * d1;
#pragma unroll
    for (int off = 16; off; off >>= 1) s += __shfl_xor_sync(0xffffffffu, s, off);
    if ((tid & 31) == 0) wsum[tid >> 5] = s;
    __syncthreads();
    if (tid == 0) {
        float t = 0.f;
#pragma unroll
        for (int i = 0; i < 8; i++) t += wsum[i];
        sval = rsqrtf(t * (1.f / DD) + 1e-5f);
    }
    __syncthreads();
    const float rstd = sval;

    out[(size_t)row * DD + tid]       = d0 * rstd * gamma[tid] + beta[tid];
    out[(size_t)row * DD + tid + 256] = d1 * rstd * gamma[tid + 256] + beta[tid + 256];
}

// ---------------- launch --------------------------------------------------
extern "C" void kernel_launch(void* const* d_in, const int* in_sizes, int n_in,
                              void* d_out, int out_size)
{
    const float* x    = (const float*)d_in[0];
    const int*   mask = (const int*)d_in[1];
    const float* Wq   = (const float*)d_in[2];
    const float* Wk   = (const float*)d_in[3];
    const float* Wv   = (const float*)d_in[4];
    const float* Wp   = (const float*)d_in[5];
    const float* W1   = (const float*)d_in[6];
    const float* b1   = (const float*)d_in[7];
    const float* W2   = (const float*)d_in[8];
    const float* b2   = (const float*)d_in[9];
    const float* ln1g = (const float*)d_in[10];
    const float* ln1b = (const float*)d_in[11];
    const float* ln2g = (const float*)d_in[12];
    const float* ln2b = (const float*)d_in[13];
    float* out = (float*)d_out;

    float *ctx, *attres, *h, *ff;
    __nv_bfloat16 *wqkvh, *wqkvl, *wph, *wpl, *w1h, *w1l, *w2h, *w2l, *qkvh, *qkvl;
    cudaGetSymbolAddress((void**)&ctx,    g_ctx);
    cudaGetSymbolAddress((void**)&attres, g_attres);
    cudaGetSymbolAddress((void**)&h,      g_h);
    cudaGetSymbolAddress((void**)&ff,     g_ff);
    cudaGetSymbolAddress((void**)&wqkvh,  g_wqkvh);
    cudaGetSymbolAddress((void**)&wqkvl,  g_wqkvl);
    cudaGetSymbolAddress((void**)&wph,    g_wph);
    cudaGetSymbolAddress((void**)&wpl,    g_wpl);
    cudaGetSymbolAddress((void**)&w1h,    g_w1h);
    cudaGetSymbolAddress((void**)&w1l,    g_w1l);
    cudaGetSymbolAddress((void**)&w2h,    g_w2h);
    cudaGetSymbolAddress((void**)&w2l,    g_w2l);
    cudaGetSymbolAddress((void**)&qkvh,   g_qkvh);
    cudaGetSymbolAddress((void**)&qkvl,   g_qkvl);

    // weight prep: single launch, y selects target
    prep_all<<<dim3(1024, 6), 256>>>(Wq, Wk, Wv, Wp, W1, W2);

    // fused QKV projection -> bf16 hi/lo (q scaled by 1/8)
    gemm_p<4><<<dim3(DD / 128, MROWS / 128, 3), 256>>>(
        x, wqkvh, wqkvl, nullptr, nullptr, nullptr, qkvh, qkvl, MROWS, DD, DD);

    // attention (tensor-core flash, pre-split bf16)
    attn_b<<<dim3(BB * HH, SS / 128), 256>>>(
        qkvh, qkvl,
        qkvh + (size_t)MROWS * DD, qkvl + (size_t)MROWS * DD,
        qkvh + 2 * (size_t)MROWS * DD, qkvl + 2 * (size_t)MROWS * DD,
        mask, ctx);

    // output projection + residual, LN1
    gemm_p<1><<<dim3(DD / 128, MROWS / 128), 256>>>(
        ctx, wph, wpl, nullptr, x, attres, nullptr, nullptr, MROWS, DD, DD);
    layernorm_k<<<MROWS, 256>>>(attres, ln1g, ln1b, h);

    // FFN
    gemm_p<2><<<dim3(DFF / 128, MROWS / 128), 256>>>(
        h, w1h, w1l, b1, nullptr, ff, nullptr, nullptr, MROWS, DFF, DD);
    gemm_p<3><<<dim3(DD / 128, MROWS / 128), 256>>>(
        ff, w2h, w2l, b2, h, attres, nullptr, nullptr, MROWS, DD, DFF);
    layernorm_k<<<MROWS, 256>>>(attres, ln2g, ln2b, out);
}

// round 17
// speedup vs baseline: 1.1034x; 1.0550x over previous
#include <cuda_runtime.h>
#include <cuda_bf16.h>
#include <math.h>
#include <stdint.h>

#define BB 4
#define SS 2048
#define DD 512
#define HH 8
#define DKK 64
#define DFF 2048
#define MROWS (BB * SS)   // 8192

// ---------------- scratch (static device globals; no allocations) ----------
__device__ float g_attres[MROWS * DD];
__device__ float g_h[MROWS * DD];
// bf16 hi/lo weights
__device__ __nv_bfloat16 g_wqkvh[3 * DD * DD];
__device__ __nv_bfloat16 g_wqkvl[3 * DD * DD];
__device__ __nv_bfloat16 g_wph[DD * DD];
__device__ __nv_bfloat16 g_wpl[DD * DD];
__device__ __nv_bfloat16 g_w1h[DFF * DD];
__device__ __nv_bfloat16 g_w1l[DFF * DD];
__device__ __nv_bfloat16 g_w2h[DD * DFF];
__device__ __nv_bfloat16 g_w2l[DD * DFF];
// bf16 hi/lo activations
__device__ __nv_bfloat16 g_xh[MROWS * DD];
__device__ __nv_bfloat16 g_xl[MROWS * DD];
__device__ __nv_bfloat16 g_qkvh[3 * MROWS * DD];
__device__ __nv_bfloat16 g_qkvl[3 * MROWS * DD];
__device__ __nv_bfloat16 g_ctxh[MROWS * DD];
__device__ __nv_bfloat16 g_ctxl[MROWS * DD];
__device__ __nv_bfloat16 g_hh[MROWS * DD];
__device__ __nv_bfloat16 g_hl[MROWS * DD];
__device__ __nv_bfloat16 g_ffh[MROWS * DFF];
__device__ __nv_bfloat16 g_ffl[MROWS * DFF];

// ================= helpers =================================================
__device__ __forceinline__ uint32_t smem_u32(const void* p) {
    uint32_t a;
    asm("{ .reg .u64 t; cvta.to.shared.u64 t, %1; cvt.u32.u64 %0, t; }"
        : "=r"(a) : "l"(p));
    return a;
}
__device__ __forceinline__ void ldm_x4(uint32_t& r0, uint32_t& r1,
                                       uint32_t& r2, uint32_t& r3, uint32_t addr) {
    asm volatile("ldmatrix.sync.aligned.m8n8.x4.shared.b16 {%0,%1,%2,%3}, [%4];"
                 : "=r"(r0), "=r"(r1), "=r"(r2), "=r"(r3) : "r"(addr));
}
__device__ __forceinline__ void ldm_x4_t(uint32_t& r0, uint32_t& r1,
                                         uint32_t& r2, uint32_t& r3, uint32_t addr) {
    asm volatile("ldmatrix.sync.aligned.m8n8.x4.trans.shared.b16 {%0,%1,%2,%3}, [%4];"
                 : "=r"(r0), "=r"(r1), "=r"(r2), "=r"(r3) : "r"(addr));
}
__device__ __forceinline__ void mma_bf16(float* d, const uint32_t* a,
                                         const uint32_t* b) {
    asm volatile(
        "mma.sync.aligned.m16n8k16.row.col.f32.bf16.bf16.f32 "
        "{%0,%1,%2,%3}, {%4,%5,%6,%7}, {%8,%9}, {%0,%1,%2,%3};"
        : "+f"(d[0]), "+f"(d[1]), "+f"(d[2]), "+f"(d[3])
        : "r"(a[0]), "r"(a[1]), "r"(a[2]), "r"(a[3]), "r"(b[0]), "r"(b[1]));
}
__device__ __forceinline__ uint32_t pack_hi(float a, float b, float& la, float& lb) {
    __nv_bfloat162 h = __floats2bfloat162_rn(a, b);
    la = a - __bfloat162float(h.x);
    lb = b - __bfloat162float(h.y);
    union { __nv_bfloat162 v; uint32_t u; } cv; cv.v = h;
    return cv.u;
}
__device__ __forceinline__ uint32_t pack_bf(float a, float b) {
    __nv_bfloat162 h = __floats2bfloat162_rn(a, b);
    union { __nv_bfloat162 v; uint32_t u; } cv; cv.v = h;
    return cv.u;
}
// 128B-row swizzle (8 x 16B chunks)
__device__ __forceinline__ uint32_t offsw(uint32_t row, uint32_t chunk) {
    return row * 128u + ((chunk ^ (row & 7u)) << 4);
}
// 64B-row swizzle (4 x 16B chunks)
__device__ __forceinline__ uint32_t offsw4(uint32_t row, uint32_t chunk) {
    return row * 64u + ((chunk ^ (row & 3u)) << 4);
}
__device__ __forceinline__ void cpa16(uint32_t dst, const void* src) {
    asm volatile("cp.async.cg.shared.global [%0], [%1], 16;"
                 :: "r"(dst), "l"(src) : "memory");
}

// ---------------- fused weight prep: fp32 -> bf16 hi/lo, 1 launch ----------
__global__ __launch_bounds__(256) void prep_all(
    const float* __restrict__ wq, const float* __restrict__ wk,
    const float* __restrict__ wv, const float* __restrict__ wp,
    const float* __restrict__ w1, const float* __restrict__ w2,
    const float* __restrict__ x)
{
    const int sel = blockIdx.y;
    const float* s;
    __nv_bfloat16 *hi, *lo;
    int n4;
    switch (sel) {
        case 0:  s = wq; hi = g_wqkvh;               lo = g_wqkvl;               n4 = DD * DD / 4;    break;
        case 1:  s = wk; hi = g_wqkvh + DD * DD;     lo = g_wqkvl + DD * DD;     n4 = DD * DD / 4;    break;
        case 2:  s = wv; hi = g_wqkvh + 2 * DD * DD; lo = g_wqkvl + 2 * DD * DD; n4 = DD * DD / 4;    break;
        case 3:  s = wp; hi = g_wph;                 lo = g_wpl;                 n4 = DD * DD / 4;    break;
        case 4:  s = w1; hi = g_w1h;                 lo = g_w1l;                 n4 = DFF * DD / 4;   break;
        case 5:  s = w2; hi = g_w2h;                 lo = g_w2l;                 n4 = DD * DFF / 4;   break;
        default: s = x;  hi = g_xh;                  lo = g_xl;                  n4 = MROWS * DD / 4; break;
    }
    const int i = blockIdx.x * 256 + threadIdx.x;
    if (i >= n4) return;
    const float4 f = *(const float4*)&s[(size_t)i * 4];
    float la, lb, lc, ld;
    uint32_t h0 = pack_hi(f.x, f.y, la, lb);
    uint32_t h1 = pack_hi(f.z, f.w, lc, ld);
    *(uint2*)&hi[(size_t)i * 4] = make_uint2(h0, h1);
    *(uint2*)&lo[(size_t)i * 4] = make_uint2(pack_bf(la, lb), pack_bf(lc, ld));
}

// ============ pure-bf16 HMMA x3 GEMM, cp.async 2-stage pipeline ============
// C[m,n] = sum_k A[m,k]*W[n,k]; A,B pre-split hi/lo bf16.
// 128x128 tile, BK=32, 8 warps (2m x 4n).
// EPI: 1 +res->f32, 3 +bias+res->f32, 4 ->bf16 hi/lo (QKV z-sel, q scaled),
//      5 +bias->GELU->bf16 hi/lo
template <int EPI>
__global__ __launch_bounds__(256, 2) void gemm_bf(
    const __nv_bfloat16* __restrict__ Ah, const __nv_bfloat16* __restrict__ Al,
    const __nv_bfloat16* __restrict__ Bh_, const __nv_bfloat16* __restrict__ Bl_,
    const float* __restrict__ bias, const float* __restrict__ res,
    float* __restrict__ C,
    __nv_bfloat16* __restrict__ Oh_, __nv_bfloat16* __restrict__ Ol_,
    int M, int N, int K)
{
    extern __shared__ __align__(16) uint8_t sm[];   // 2 x 32768
    const uint32_t sb = smem_u32(sm);
    const uint32_t AH = 0, AL = 8192, BH = 16384, BL = 24576;

    const int tid = threadIdx.x;
    const int lane = tid & 31;
    const int warp = tid >> 5;
    const int wm = warp >> 2;
    const int wn = warp & 3;
    const int bm = blockIdx.y * 128;
    const int bn = blockIdx.x * 128;

    const __nv_bfloat16* Bh = Bh_;
    const __nv_bfloat16* Bl = Bl_;
    __nv_bfloat16* Oh = Oh_;
    __nv_bfloat16* Ol = Ol_;
    float scale = 1.f;
    if (EPI == 4) {
        const int z = blockIdx.z;
        Bh += (size_t)z * N * K; Bl += (size_t)z * N * K;
        Oh += (size_t)z * M * N; Ol += (size_t)z * M * N;
        if (z == 0) scale = 0.125f;
    }

    float acc[4][4][4];
#pragma unroll
    for (int i = 0; i < 4; i++)
#pragma unroll
        for (int j = 0; j < 4; j++)
#pragma unroll
            for (int e = 0; e < 4; e++) acc[i][j][e] = 0.f;

    const int arow = lane & 15;
    const int akc  = lane >> 4;
    const int brow = ((lane >> 4) << 3) + (lane & 7);
    const int bkc  = (lane >> 3) & 1;
    const uint32_t asw = (uint32_t)(arow & 3);
    const uint32_t bsw = (uint32_t)(brow & 3);

    // load-slot mapping: 512 slots = 128 rows x 4 chunks, 2 per thread
    const int sr0 = tid >> 2,          sc0 = tid & 3;
    const int sr1 = (tid + 256) >> 2,  sc1 = tid & 3;
    const uint32_t so0 = offsw4((uint32_t)sr0, (uint32_t)sc0);
    const uint32_t so1 = offsw4((uint32_t)sr1, (uint32_t)sc1);

    const int nslab = K >> 5;

    // prologue: issue slab 0 into stage 0
    {
        const size_t ga0 = (size_t)(bm + sr0) * K + sc0 * 8;
        const size_t ga1 = (size_t)(bm + sr1) * K + sc1 * 8;
        const size_t gb0 = (size_t)(bn + sr0) * K + sc0 * 8;
        const size_t gb1 = (size_t)(bn + sr1) * K + sc1 * 8;
        cpa16(sb + AH + so0, Ah + ga0); cpa16(sb + AH + so1, Ah + ga1);
        cpa16(sb + AL + so0, Al + ga0); cpa16(sb + AL + so1, Al + ga1);
        cpa16(sb + BH + so0, Bh + gb0); cpa16(sb + BH + so1, Bh + gb1);
        cpa16(sb + BL + so0, Bl + gb0); cpa16(sb + BL + so1, Bl + gb1);
        asm volatile("cp.async.commit_group;" ::: "memory");
    }

    for (int t = 0; t < nslab; t++) {
        const uint32_t base = sb + (uint32_t)(t & 1) * 32768u;

        if (t + 1 < nslab) {
            const uint32_t nb = sb + (uint32_t)((t + 1) & 1) * 32768u;
            const int k0 = (t + 1) << 5;
            const size_t ga0 = (size_t)(bm + sr0) * K + k0 + sc0 * 8;
            const size_t ga1 = (size_t)(bm + sr1) * K + k0 + sc1 * 8;
            const size_t gb0 = (size_t)(bn + sr0) * K + k0 + sc0 * 8;
            const size_t gb1 = (size_t)(bn + sr1) * K + k0 + sc1 * 8;
            cpa16(nb + AH + so0, Ah + ga0); cpa16(nb + AH + so1, Ah + ga1);
            cpa16(nb + AL + so0, Al + ga0); cpa16(nb + AL + so1, Al + ga1);
            cpa16(nb + BH + so0, Bh + gb0); cpa16(nb + BH + so1, Bh + gb1);
            cpa16(nb + BL + so0, Bl + gb0); cpa16(nb + BL + so1, Bl + gb1);
            asm volatile("cp.async.commit_group;" ::: "memory");
            asm volatile("cp.async.wait_group 1;" ::: "memory");
        } else {
            asm volatile("cp.async.wait_group 0;" ::: "memory");
        }
        __syncthreads();

        // ---- mma phase: 2 k-steps of 16 ----
#pragma unroll
        for (int ks = 0; ks < 2; ks++) {
            const uint32_t kca = (uint32_t)(ks * 2 + akc);
            const uint32_t kcb = (uint32_t)(ks * 2 + bkc);

            uint32_t bh[2][4], bl[2][4];
#pragma unroll
            for (int p = 0; p < 2; p++) {
                const uint32_t row = (uint32_t)(wn * 32 + p * 16 + brow);
                const uint32_t off = row * 64 + ((kcb ^ bsw) << 4);
                ldm_x4(bh[p][0], bh[p][1], bh[p][2], bh[p][3], base + BH + off);
                ldm_x4(bl[p][0], bl[p][1], bl[p][2], bl[p][3], base + BL + off);
            }
#pragma unroll
            for (int mf = 0; mf < 4; mf++) {
                const uint32_t row = (uint32_t)(wm * 64 + mf * 16 + arow);
                const uint32_t off = row * 64 + ((kca ^ asw) << 4);
                uint32_t ah[4], al[4];
                ldm_x4(ah[0], ah[1], ah[2], ah[3], base + AH + off);
                ldm_x4(al[0], al[1], al[2], al[3], base + AL + off);
#pragma unroll
                for (int nf = 0; nf < 4; nf++) {
                    uint32_t* bhp = &bh[nf >> 1][(nf & 1) * 2];
                    uint32_t* blp = &bl[nf >> 1][(nf & 1) * 2];
                    mma_bf16(acc[mf][nf], ah, bhp);
                    mma_bf16(acc[mf][nf], ah, blp);
                    mma_bf16(acc[mf][nf], al, bhp);
                }
            }
        }
        __syncthreads();   // all reads done before next issue overwrites
    }

    // ---- epilogue ----
#pragma unroll
    for (int mf = 0; mf < 4; mf++) {
#pragma unroll
        for (int nf = 0; nf < 4; nf++) {
            const int r0 = bm + wm * 64 + mf * 16 + (lane >> 2);
            const int cc = bn + wn * 32 + nf * 8 + (lane & 3) * 2;
#pragma unroll
            for (int half = 0; half < 2; half++) {
                const int m = r0 + half * 8;
                float2 v = make_float2(acc[mf][nf][half * 2],
                                       acc[mf][nf][half * 2 + 1]);
                if (EPI == 1) {
                    const float2 r = *(const float2*)&res[(size_t)m * N + cc];
                    v.x += r.x; v.y += r.y;
                    *(float2*)&C[(size_t)m * N + cc] = v;
                }
                if (EPI == 3) {
                    const float2 bb = *(const float2*)&bias[cc];
                    const float2 r = *(const float2*)&res[(size_t)m * N + cc];
                    v.x += bb.x + r.x; v.y += bb.y + r.y;
                    *(float2*)&C[(size_t)m * N + cc] = v;
                }
                if (EPI == 4) {
                    const float a = v.x * scale, b = v.y * scale;
                    float la, lb;
                    const uint32_t hh = pack_hi(a, b, la, lb);
                    *(uint32_t*)&Oh[(size_t)m * N + cc] = hh;
                    *(uint32_t*)&Ol[(size_t)m * N + cc] = pack_bf(la, lb);
                }
                if (EPI == 5) {
                    const float2 bb = *(const float2*)&bias[cc];
                    v.x += bb.x; v.y += bb.y;
                    v.x = 0.5f * v.x * (1.f + erff(v.x * 0.70710678118654752f));
                    v.y = 0.5f * v.y * (1.f + erff(v.y * 0.70710678118654752f));
                    float la, lb;
                    const uint32_t hh = pack_hi(v.x, v.y, la, lb);
                    *(uint32_t*)&Oh[(size_t)m * N + cc] = hh;
                    *(uint32_t*)&Ol[(size_t)m * N + cc] = pack_bf(la, lb);
                }
            }
        }
    }
}

// ============ HMMA bf16x3 flash attention (pre-split bf16 in AND out) ======
__global__ __launch_bounds__(256) void attn_b(
    const __nv_bfloat16* __restrict__ Qh_g, const __nv_bfloat16* __restrict__ Ql_g,
    const __nv_bfloat16* __restrict__ Kh_g, const __nv_bfloat16* __restrict__ Kl_g,
    const __nv_bfloat16* __restrict__ Vh_g, const __nv_bfloat16* __restrict__ Vl_g,
    const int* __restrict__ mask,
    __nv_bfloat16* __restrict__ Ch, __nv_bfloat16* __restrict__ Cl)
{
    __shared__ __align__(16) uint8_t sm[32768 + 256];
    const uint32_t sb = smem_u32(sm);
    const uint32_t KH = 0, KL = 8192, VH = 16384, VL = 24576, MB = 32768;
    float* mbf = (float*)(sm + MB);

    const int tid = threadIdx.x;
    const int lane = tid & 31;
    const int warp = tid >> 5;
    const int bh = blockIdx.x;
    const int b = bh / HH, h = bh % HH;
    const int bm = blockIdx.y * 128;

    // ---- stage Q hi/lo (raw copy), ldmatrix to regs ----
#pragma unroll
    for (int i = 0; i < 4; i++) {
        const int slot = tid + i * 256;
        const int r = slot >> 3, ch = slot & 7;
        const size_t gq = (size_t)(b * SS + bm + r) * DD + h * DKK + ch * 8;
        const uint32_t off = offsw((uint32_t)r, (uint32_t)ch);
        *(uint4*)(sm + off)         = *(const uint4*)&Qh_g[gq];
        *(uint4*)(sm + 16384 + off) = *(const uint4*)&Ql_g[gq];
    }
    __syncthreads();

    const int arow = lane & 15;
    const int akc  = lane >> 4;
    uint32_t Qh[4][4], Ql[4][4];
    {
        const uint32_t row = (uint32_t)(warp * 16 + arow);
#pragma unroll
        for (int kc = 0; kc < 4; kc++) {
            const uint32_t off = offsw(row, (uint32_t)(kc * 2 + akc));
            ldm_x4(Qh[kc][0], Qh[kc][1], Qh[kc][2], Qh[kc][3], sb + off);
            ldm_x4(Ql[kc][0], Ql[kc][1], Ql[kc][2], Ql[kc][3], sb + 16384 + off);
        }
    }
    __syncthreads();

    const int brow = ((lane >> 4) << 3) + (lane & 7);
    const int bkc  = (lane >> 3) & 1;
    const int vkey = lane & 15;
    const int vch  = lane >> 4;

    float S[8][4], Ofr[8][4];
#pragma unroll
    for (int nf = 0; nf < 8; nf++)
#pragma unroll
        for (int e = 0; e < 4; e++) Ofr[nf][e] = 0.f;
    float m0 = -1e30f, m1 = -1e30f, l0 = 0.f, l1 = 0.f;

    for (int t0 = 0; t0 < SS; t0 += 64) {
#pragma unroll
        for (int i = 0; i < 2; i++) {
            const int slot = tid + i * 256;
            const int r = slot >> 3, ch = slot & 7;
            const size_t g = (size_t)(b * SS + t0 + r) * DD + h * DKK + ch * 8;
            const uint32_t off = offsw((uint32_t)r, (uint32_t)ch);
            *(uint4*)(sm + KH + off) = *(const uint4*)&Kh_g[g];
            *(uint4*)(sm + KL + off) = *(const uint4*)&Kl_g[g];
            *(uint4*)(sm + VH + off) = *(const uint4*)&Vh_g[g];
            *(uint4*)(sm + VL + off) = *(const uint4*)&Vl_g[g];
        }
        if (tid < 64) mbf[tid] = mask[b * SS + t0 + tid] ? 0.f : -100.f;
        __syncthreads();

#pragma unroll
        for (int nf = 0; nf < 8; nf++)
#pragma unroll
            for (int e = 0; e < 4; e++) S[nf][e] = 0.f;

#pragma unroll
        for (int p = 0; p < 4; p++) {
#pragma unroll
            for (int kc = 0; kc < 4; kc++) {
                const uint32_t row = (uint32_t)(p * 16 + brow);
                const uint32_t off = offsw(row, (uint32_t)(kc * 2 + bkc));
                uint32_t kh[4], kl[4];
                ldm_x4(kh[0], kh[1], kh[2], kh[3], sb + KH + off);
                ldm_x4(kl[0], kl[1], kl[2], kl[3], sb + KL + off);
                mma_bf16(S[p * 2],     Qh[kc], &kh[0]);
                mma_bf16(S[p * 2 + 1], Qh[kc], &kh[2]);
                mma_bf16(S[p * 2],     Qh[kc], &kl[0]);
                mma_bf16(S[p * 2 + 1], Qh[kc], &kl[2]);
                mma_bf16(S[p * 2],     Ql[kc], &kh[0]);
                mma_bf16(S[p * 2 + 1], Ql[kc], &kh[2]);
            }
        }

        float cm0 = -1e30f, cm1 = -1e30f;
#pragma unroll
        for (int nf = 0; nf < 8; nf++) {
            const float2 mv = *(const float2*)&mbf[nf * 8 + (lane & 3) * 2];
            S[nf][0] += mv.x; S[nf][1] += mv.y;
            S[nf][2] += mv.x; S[nf][3] += mv.y;
            cm0 = fmaxf(cm0, fmaxf(S[nf][0], S[nf][1]));
            cm1 = fmaxf(cm1, fmaxf(S[nf][2], S[nf][3]));
        }
        cm0 = fmaxf(cm0, __shfl_xor_sync(0xffffffffu, cm0, 1));
        cm0 = fmaxf(cm0, __shfl_xor_sync(0xffffffffu, cm0, 2));
        cm1 = fmaxf(cm1, __shfl_xor_sync(0xffffffffu, cm1, 1));
        cm1 = fmaxf(cm1, __shfl_xor_sync(0xffffffffu, cm1, 2));

        const float mn0 = fmaxf(m0, cm0);
        const float mn1 = fmaxf(m1, cm1);
        const float c0 = __expf(m0 - mn0);
        const float c1 = __expf(m1 - mn1);
        m0 = mn0; m1 = mn1;
        l0 *= c0; l1 *= c1;
#pragma unroll
        for (int nf = 0; nf < 8; nf++) {
            Ofr[nf][0] *= c0; Ofr[nf][1] *= c0;
            Ofr[nf][2] *= c1; Ofr[nf][3] *= c1;
        }
#pragma unroll
        for (int nf = 0; nf < 8; nf++) {
            S[nf][0] = __expf(S[nf][0] - mn0);
            S[nf][1] = __expf(S[nf][1] - mn0);
            S[nf][2] = __expf(S[nf][2] - mn1);
            S[nf][3] = __expf(S[nf][3] - mn1);
            l0 += S[nf][0] + S[nf][1];
            l1 += S[nf][2] + S[nf][3];
        }

#pragma unroll
        for (int kcp = 0; kcp < 4; kcp++) {
            uint32_t Ah[4], Al[4];
            float ra, rb;
            Ah[0] = pack_hi(S[kcp * 2][0],     S[kcp * 2][1],     ra, rb); Al[0] = pack_bf(ra, rb);
            Ah[1] = pack_hi(S[kcp * 2][2],     S[kcp * 2][3],     ra, rb); Al[1] = pack_bf(ra, rb);
            Ah[2] = pack_hi(S[kcp * 2 + 1][0], S[kcp * 2 + 1][1], ra, rb); Al[2] = pack_bf(ra, rb);
            Ah[3] = pack_hi(S[kcp * 2 + 1][2], S[kcp * 2 + 1][3], ra, rb); Al[3] = pack_bf(ra, rb);
#pragma unroll
            for (int vv = 0; vv < 4; vv++) {
                const uint32_t off = offsw((uint32_t)(kcp * 16 + vkey),
                                           (uint32_t)(vv * 2 + vch));
                uint32_t vh[4], vl[4];
                ldm_x4_t(vh[0], vh[1], vh[2], vh[3], sb + VH + off);
                ldm_x4_t(vl[0], vl[1], vl[2], vl[3], sb + VL + off);
                mma_bf16(Ofr[vv * 2],     Ah, &vh[0]);
                mma_bf16(Ofr[vv * 2 + 1], Ah, &vh[2]);
                mma_bf16(Ofr[vv * 2],     Ah, &vl[0]);
                mma_bf16(Ofr[vv * 2 + 1], Ah, &vl[2]);
                mma_bf16(Ofr[vv * 2],     Al, &vh[0]);
                mma_bf16(Ofr[vv * 2 + 1], Al, &vh[2]);
            }
        }
        __syncthreads();
    }

    // ---- finalize: write ctx as bf16 hi/lo ----
    l0 += __shfl_xor_sync(0xffffffffu, l0, 1);
    l0 += __shfl_xor_sync(0xffffffffu, l0, 2);
    l1 += __shfl_xor_sync(0xffffffffu, l1, 1);
    l1 += __shfl_xor_sync(0xffffffffu, l1, 2);
    const float i0 = 1.f / l0, i1 = 1.f / l1;

    const int r0 = b * SS + bm + warp * 16 + (lane >> 2);
#pragma unroll
    for (int nf = 0; nf < 8; nf++) {
        const int col = h * DKK + nf * 8 + (lane & 3) * 2;
        float la, lb;
        uint32_t hh = pack_hi(Ofr[nf][0] * i0, Ofr[nf][1] * i0, la, lb);
        *(uint32_t*)&Ch[(size_t)r0 * DD + col] = hh;
        *(uint32_t*)&Cl[(size_t)r0 * DD + col] = pack_bf(la, lb);
        hh = pack_hi(Ofr[nf][2] * i1, Ofr[nf][3] * i1, la, lb);
        *(uint32_t*)&Ch[(size_t)(r0 + 8) * DD + col] = hh;
        *(uint32_t*)&Cl[(size_t)(r0 + 8) * DD + col] = pack_bf(la, lb);
    }
}

// ---------------- layernorm; optionally also emit bf16 hi/lo ---------------
__global__ __launch_bounds__(256) void layernorm_k(
    const float* __restrict__ in, const float* __restrict__ gamma,
    const float* __restrict__ beta, float* __restrict__ out,
    __nv_bfloat16* __restrict__ oh, __nv_bfloat16* __restrict__ ol)
{
    const int row = blockIdx.x;
    const int tid = threadIdx.x;
    const float* xr = in + (size_t)row * DD;

    const float x0 = xr[tid];
    const float x1 = xr[tid + 256];

    __shared__ float wsum[8];
    __shared__ float sval;

    float s = x0 + x1;
#pragma unroll
    for (int off = 16; off; off >>= 1) s += __shfl_xor_sync(0xffffffffu, s, off);
    if ((tid & 31) == 0) wsum[tid >> 5] = s;
    __syncthreads();
    if (tid == 0) {
        float t = 0.f;
#pragma unroll
        for (int i = 0; i < 8; i++) t += wsum[i];
        sval = t * (1.f / DD);
    }
    __syncthreads();
    const float mu = sval;
    __syncthreads();

    const float d0 = x0 - mu, d1 = x1 - mu;
    s = d0 * d0 + d1 * d1;
#pragma unroll
    for (int off = 16; off; off >>= 1) s += __shfl_xor_sync(0xffffffffu, s, off);
    if ((tid & 31) == 0) wsum[tid >> 5] = s;
    __syncthreads();
    if (tid == 0) {
        float t = 0.f;
#pragma unroll
        for (int i = 0; i < 8; i++) t += wsum[i];
        sval = rsqrtf(t * (1.f / DD) + 1e-5f);
    }
    __syncthreads();
    const float rstd = sval;

    const float o0 = d0 * rstd * gamma[tid] + beta[tid];
    const float o1 = d1 * rstd * gamma[tid + 256] + beta[tid + 256];
    out[(size_t)row * DD + tid]       = o0;
    out[(size_t)row * DD + tid + 256] = o1;
    if (oh) {
        const __nv_bfloat16 h0 = __float2bfloat16_rn(o0);
        const __nv_bfloat16 h1 = __float2bfloat16_rn(o1);
        oh[(size_t)row * DD + tid]       = h0;
        oh[(size_t)row * DD + tid + 256] = h1;
        ol[(size_t)row * DD + tid]       = __float2bfloat16_rn(o0 - __bfloat162float(h0));
        ol[(size_t)row * DD + tid + 256] = __float2bfloat16_rn(o1 - __bfloat162float(h1));
    }
}

// ---------------- launch --------------------------------------------------
extern "C" void kernel_launch(void* const* d_in, const int* in_sizes, int n_in,
                              void* d_out, int out_size)
{
    const float* x    = (const float*)d_in[0];
    const int*   mask = (const int*)d_in[1];
    const float* Wq   = (const float*)d_in[2];
    const float* Wk   = (const float*)d_in[3];
    const float* Wv   = (const float*)d_in[4];
    const float* Wp   = (const float*)d_in[5];
    const float* W1   = (const float*)d_in[6];
    const float* b1   = (const float*)d_in[7];
    const float* W2   = (const float*)d_in[8];
    const float* b2   = (const float*)d_in[9];
    const float* ln1g = (const float*)d_in[10];
    const float* ln1b = (const float*)d_in[11];
    const float* ln2g = (const float*)d_in[12];
    const float* ln2b = (const float*)d_in[13];
    float* out = (float*)d_out;

    float *attres, *h;
    __nv_bfloat16 *wqkvh, *wqkvl, *wph, *wpl, *w1h, *w1l, *w2h, *w2l;
    __nv_bfloat16 *xh, *xl, *qkvh, *qkvl, *ctxh, *ctxl, *hh, *hl, *ffh, *ffl;
    cudaGetSymbolAddress((void**)&attres, g_attres);
    cudaGetSymbolAddress((void**)&h,      g_h);
    cudaGetSymbolAddress((void**)&wqkvh,  g_wqkvh);
    cudaGetSymbolAddress((void**)&wqkvl,  g_wqkvl);
    cudaGetSymbolAddress((void**)&wph,    g_wph);
    cudaGetSymbolAddress((void**)&wpl,    g_wpl);
    cudaGetSymbolAddress((void**)&w1h,    g_w1h);
    cudaGetSymbolAddress((void**)&w1l,    g_w1l);
    cudaGetSymbolAddress((void**)&w2h,    g_w2h);
    cudaGetSymbolAddress((void**)&w2l,    g_w2l);
    cudaGetSymbolAddress((void**)&xh,     g_xh);
    cudaGetSymbolAddress((void**)&xl,     g_xl);
    cudaGetSymbolAddress((void**)&qkvh,   g_qkvh);
    cudaGetSymbolAddress((void**)&qkvl,   g_qkvl);
    cudaGetSymbolAddress((void**)&ctxh,   g_ctxh);
    cudaGetSymbolAddress((void**)&ctxl,   g_ctxl);
    cudaGetSymbolAddress((void**)&hh,     g_hh);
    cudaGetSymbolAddress((void**)&hl,     g_hl);
    cudaGetSymbolAddress((void**)&ffh,    g_ffh);
    cudaGetSymbolAddress((void**)&ffl,    g_ffl);

    cudaFuncSetAttribute(gemm_bf<1>, cudaFuncAttributeMaxDynamicSharedMemorySize, 65536);
    cudaFuncSetAttribute(gemm_bf<3>, cudaFuncAttributeMaxDynamicSharedMemorySize, 65536);
    cudaFuncSetAttribute(gemm_bf<4>, cudaFuncAttributeMaxDynamicSharedMemorySize, 65536);
    cudaFuncSetAttribute(gemm_bf<5>, cudaFuncAttributeMaxDynamicSharedMemorySize, 65536);

    // prep: weights + x -> bf16 hi/lo (y=6 handles x, 4096 blocks wide)
    prep_all<<<dim3(4096, 7), 256>>>(Wq, Wk, Wv, Wp, W1, W2, x);

    // fused QKV projection -> bf16 hi/lo (q scaled by 1/8)
    gemm_bf<4><<<dim3(DD / 128, MROWS / 128, 3), 256, 65536>>>(
        xh, xl, wqkvh, wqkvl, nullptr, nullptr, nullptr, qkvh, qkvl, MROWS, DD, DD);

    // attention -> ctx bf16 hi/lo
    attn_b<<<dim3(BB * HH, SS / 128), 256>>>(
        qkvh, qkvl,
        qkvh + (size_t)MROWS * DD, qkvl + (size_t)MROWS * DD,
        qkvh + 2 * (size_t)MROWS * DD, qkvl + 2 * (size_t)MROWS * DD,
        mask, ctxh, ctxl);

    // output projection + residual -> fp32, LN1 (emits fp32 + bf16 hi/lo)
    gemm_bf<1><<<dim3(DD / 128, MROWS / 128), 256, 65536>>>(
        ctxh, ctxl, wph, wpl, nullptr, x, attres, nullptr, nullptr, MROWS, DD, DD);
    layernorm_k<<<MROWS, 256>>>(attres, ln1g, ln1b, h, hh, hl);

    // FFN1: bias+GELU -> bf16 hi/lo
    gemm_bf<5><<<dim3(DFF / 128, MROWS / 128), 256, 65536>>>(
        hh, hl, w1h, w1l, b1, nullptr, nullptr, ffh, ffl, MROWS, DFF, DD);
    // FFN2: bias + residual(h) -> fp32
    gemm_bf<3><<<dim3(DD / 128, MROWS / 128), 256, 65536>>>(
        ffh, ffl, w2h, w2l, b2, h, attres, nullptr, nullptr, MROWS, DD, DFF);
    layernorm_k<<<MROWS, 256>>>(attres, ln2g, ln2b, out, nullptr, nullptr);
}